// round 6
// baseline (speedup 1.0000x reference)
#include <cuda_runtime.h>
#include <math.h>
#include <stdint.h>

#define SEQ 2048
#define HID 2048
#define NH  16
#define NKV 8
#define HD  128

// Scratch (allocation-free: __device__ globals)
__device__ float g_q[(size_t)SEQ * NH * HD];
__device__ float g_k[(size_t)SEQ * NKV * HD];
__device__ float g_v[(size_t)SEQ * NKV * HD];
__device__ float g_scores[(size_t)NH * SEQ * SEQ];
__device__ float g_ctx[(size_t)SEQ * NH * HD];

// ---------------------------------------------------------------------------
// helpers
// ---------------------------------------------------------------------------
__device__ __forceinline__ void cpasync16(uint32_t s, const float* g) {
    asm volatile("cp.async.cg.shared.global [%0], [%1], 16;\n" :: "r"(s), "l"(g));
}
__device__ __forceinline__ uint32_t f2tf32(float f) {
    uint32_t r;
    asm("cvt.rna.tf32.f32 %0, %1;" : "=r"(r) : "f"(f));
    return r;
}
__device__ __forceinline__ void mma_tf32(float* c, const uint32_t* a, const uint32_t* b) {
    asm volatile(
        "mma.sync.aligned.m16n8k8.row.col.f32.tf32.tf32.f32 "
        "{%0,%1,%2,%3}, {%4,%5,%6,%7}, {%8,%9}, {%0,%1,%2,%3};"
        : "+f"(c[0]), "+f"(c[1]), "+f"(c[2]), "+f"(c[3])
        : "r"(a[0]), "r"(a[1]), "r"(a[2]), "r"(a[3]), "r"(b[0]), "r"(b[1]));
}

// ---------------------------------------------------------------------------
// Batched TF32 tensor-core GEMM.
//   NT (TB_NT=true):  C[m,n] = sum_k A[m,k] * B[n,k]
//   NN (TB_NT=false): C[m,n] = sum_k A[m,k] * B[k,n]
// Batch offsets: A += bz*sA, B += (bz/bdiv)*sB, C += bz*sC.
// causalSkip: skip tiles fully above the diagonal (score GEMM).
// causalKlim: clamp K-loop to m0+128 (context GEMM).
// M, N mult of 128; K mult of 16.
// ---------------------------------------------------------------------------
#define BM 128
#define BN 128
#define BK 16
#define A_STRIDE 20          // floats per smem row (conflict-free, 16B aligned)
#define A_STAGE  (BM * A_STRIDE)       // 2560
#define BNT_STAGE (BN * A_STRIDE)      // 2560
#define BNN_STRIDE 136
#define BNN_STAGE (BK * BNN_STRIDE)    // 2176

template <bool TB_NT>
__global__ __launch_bounds__(256)
void gemm_tf32(const float* __restrict__ A, const float* __restrict__ B,
               float* __restrict__ C,
               int M, int N, int K, int lda, int ldb, int ldc,
               long long sA_, long long sB_, long long sC_, int bdiv,
               int causalSkip, int causalKlim)
{
    const int bz = blockIdx.z;
    A += (long long)bz * sA_;
    B += (long long)(bz / bdiv) * sB_;
    C += (long long)bz * sC_;

    const int m0 = blockIdx.y * BM;
    const int n0 = blockIdx.x * BN;
    if (causalSkip && n0 > m0 + BM - 1) return;
    int Keff = K;
    if (causalKlim) Keff = min(K, m0 + BM);

    __shared__ float sA[2][A_STAGE];
    __shared__ float sB[2][BNT_STAGE];   // NN uses first BNN_STAGE floats

    const int tid  = threadIdx.x;
    const int wid  = tid >> 5;
    const int lane = tid & 31;
    const int wm   = wid & 1;       // 0..1 -> m offset wm*64
    const int wn   = wid >> 1;      // 0..3 -> n offset wn*32
    const int lrow = lane >> 2;     // 0..7
    const int lcol = lane & 3;      // 0..3

    // global-load addressing (2 x float4 per thread per stage per matrix)
    // A tile: 128 rows x 16 cols
    const int a_r0 = tid >> 1;                  // NO: need 512 f4 / 256 thr = 2 each
    (void)a_r0;

    float acc[4][4][4];
    #pragma unroll
    for (int i = 0; i < 4; i++)
        #pragma unroll
        for (int j = 0; j < 4; j++)
            #pragma unroll
            for (int r = 0; r < 4; r++) acc[i][j][r] = 0.0f;

    uint32_t sA_base = (uint32_t)__cvta_generic_to_shared(&sA[0][0]);
    uint32_t sB_base = (uint32_t)__cvta_generic_to_shared(&sB[0][0]);

    auto load_stage = [&](int buf, int k0) {
        // A: 128x16 floats = 512 float4; thread does idx = tid, tid+256
        #pragma unroll
        for (int i = 0; i < 2; i++) {
            int idx = tid + i * 256;
            int row = idx >> 2;              // 0..127
            int c4  = (idx & 3) << 2;        // 0,4,8,12
            cpasync16(sA_base + (buf * A_STAGE + row * A_STRIDE + c4) * 4,
                      A + (long long)(m0 + row) * lda + k0 + c4);
        }
        if (TB_NT) {
            // B: rows n0..n0+127, cols k0..k0+15 -> sB[n][k]
            #pragma unroll
            for (int i = 0; i < 2; i++) {
                int idx = tid + i * 256;
                int row = idx >> 2;
                int c4  = (idx & 3) << 2;
                cpasync16(sB_base + (buf * BNT_STAGE + row * A_STRIDE + c4) * 4,
                          B + (long long)(n0 + row) * ldb + k0 + c4);
            }
        } else {
            // B: rows k0..k0+15, cols n0..n0+127 -> sB[k][n]
            #pragma unroll
            for (int i = 0; i < 2; i++) {
                int idx = tid + i * 256;
                int kr  = idx >> 5;              // 0..15
                int n4  = (idx & 31) << 2;       // 0..124
                cpasync16(sB_base + (buf * BNT_STAGE + kr * BNN_STRIDE + n4) * 4,
                          B + (long long)(k0 + kr) * ldb + n0 + n4);
            }
        }
        asm volatile("cp.async.commit_group;\n" ::);
    };

    load_stage(0, 0);
    int buf = 0;

    for (int k0 = 0; k0 < Keff; k0 += BK) {
        const bool has_next = (k0 + BK) < Keff;
        if (has_next) load_stage(buf ^ 1, k0 + BK);
        if (has_next) asm volatile("cp.async.wait_group 1;\n" ::);
        else          asm volatile("cp.async.wait_group 0;\n" ::);
        __syncthreads();

        const float* aS = sA[buf];
        const float* bS = sB[buf];

        #pragma unroll
        for (int ks = 0; ks < 2; ks++) {
            uint32_t af[4][4];
            #pragma unroll
            for (int mt = 0; mt < 4; mt++) {
                const int r = wm * 64 + mt * 16 + lrow;
                const int c = ks * 8 + lcol;
                af[mt][0] = f2tf32(aS[r * A_STRIDE + c]);
                af[mt][1] = f2tf32(aS[(r + 8) * A_STRIDE + c]);
                af[mt][2] = f2tf32(aS[r * A_STRIDE + c + 4]);
                af[mt][3] = f2tf32(aS[(r + 8) * A_STRIDE + c + 4]);
            }
            uint32_t bf[4][2];
            #pragma unroll
            for (int nt = 0; nt < 4; nt++) {
                const int n = wn * 32 + nt * 8 + lrow;
                const int kk = ks * 8 + lcol;
                if (TB_NT) {
                    bf[nt][0] = f2tf32(bS[n * A_STRIDE + kk]);
                    bf[nt][1] = f2tf32(bS[n * A_STRIDE + kk + 4]);
                } else {
                    bf[nt][0] = f2tf32(bS[kk * BNN_STRIDE + n]);
                    bf[nt][1] = f2tf32(bS[(kk + 4) * BNN_STRIDE + n]);
                }
            }
            #pragma unroll
            for (int mt = 0; mt < 4; mt++)
                #pragma unroll
                for (int nt = 0; nt < 4; nt++)
                    mma_tf32(acc[mt][nt], af[mt], bf[nt]);
        }
        __syncthreads();
        buf ^= 1;
    }

    // epilogue
    #pragma unroll
    for (int mt = 0; mt < 4; mt++) {
        const int r = m0 + wm * 64 + mt * 16 + lrow;
        #pragma unroll
        for (int nt = 0; nt < 4; nt++) {
            const int c = n0 + wn * 32 + nt * 8 + lcol * 2;
            float2 v0 = make_float2(acc[mt][nt][0], acc[mt][nt][1]);
            float2 v1 = make_float2(acc[mt][nt][2], acc[mt][nt][3]);
            *(float2*)(C + (long long)r * ldc + c)       = v0;
            *(float2*)(C + (long long)(r + 8) * ldc + c) = v1;
        }
    }
}

// ---------------------------------------------------------------------------
// RoPE (rotate-half), in-place on [S, heads, 128]
// ---------------------------------------------------------------------------
__global__ void rope_kernel(float* __restrict__ t,
                            const float* __restrict__ cosT,
                            const float* __restrict__ sinT, int heads)
{
    const int idx = blockIdx.x * blockDim.x + threadIdx.x;
    const int total = SEQ * heads * (HD / 2);
    if (idx >= total) return;
    const int d = idx % (HD / 2);
    const int h = (idx / (HD / 2)) % heads;
    const int s = idx / ((HD / 2) * heads);

    const float c1 = cosT[s * HD + d];
    const float s1 = sinT[s * HD + d];
    const float c2 = cosT[s * HD + d + HD / 2];
    const float s2 = sinT[s * HD + d + HD / 2];

    float* row = t + (long long)s * heads * HD + h * HD;
    const float x1 = row[d];
    const float x2 = row[d + HD / 2];
    row[d]          = x1 * c1 - x2 * s1;
    row[d + HD / 2] = x2 * c2 + x1 * s2;
}

// ---------------------------------------------------------------------------
// Causal softmax (applies 1/sqrt(D); zero-fills masked tail)
// ---------------------------------------------------------------------------
__global__ __launch_bounds__(256)
void softmax_kernel(float* __restrict__ scores)
{
    const int q = blockIdx.x;
    const int h = blockIdx.y;
    float* row = scores + ((size_t)h * SEQ + q) * SEQ;
    const int tid = threadIdx.x;
    const float scale = 0.08838834764831845f;
    const int n = q + 1;

    __shared__ float red[256];

    float mx = -INFINITY;
    for (int k = tid; k < n; k += 256) mx = fmaxf(mx, row[k] * scale);
    red[tid] = mx;
    __syncthreads();
    for (int st = 128; st > 0; st >>= 1) {
        if (tid < st) red[tid] = fmaxf(red[tid], red[tid + st]);
        __syncthreads();
    }
    mx = red[0];
    __syncthreads();

    float sum = 0.0f;
    for (int k = tid; k < n; k += 256) {
        const float e = __expf(row[k] * scale - mx);
        row[k] = e;
        sum += e;
    }
    red[tid] = sum;
    __syncthreads();
    for (int st = 128; st > 0; st >>= 1) {
        if (tid < st) red[tid] += red[tid + st];
        __syncthreads();
    }
    const float inv = 1.0f / red[0];
    __syncthreads();

    for (int k = tid; k < n; k += 256) row[k] *= inv;
    for (int k = n + tid; k < SEQ; k += 256) row[k] = 0.0f;
}

// ---------------------------------------------------------------------------
extern "C" void kernel_launch(void* const* d_in, const int* in_sizes, int n_in,
                              void* d_out, int out_size)
{
    const float* x    = (const float*)d_in[0];
    const float* Wq   = (const float*)d_in[1];
    const float* Wk   = (const float*)d_in[2];
    const float* Wv   = (const float*)d_in[3];
    const float* Wo   = (const float*)d_in[4];
    const float* cosT = (const float*)d_in[5];
    const float* sinT = (const float*)d_in[6];
    float* out = (float*)d_out;

    float* q   = g_q;
    float* k   = g_k;
    float* v   = g_v;
    float* sc  = g_scores;
    float* ctx = g_ctx;

    const dim3 blk(256);

    // QKV projections (NT)
    gemm_tf32<true><<<dim3(16, 16, 1), blk>>>(x, Wq, q, SEQ, 2048, HID,
                                              HID, HID, 2048, 0, 0, 0, 1, 0, 0);
    gemm_tf32<true><<<dim3(8, 16, 1), blk>>>(x, Wk, k, SEQ, 1024, HID,
                                             HID, HID, 1024, 0, 0, 0, 1, 0, 0);
    gemm_tf32<true><<<dim3(8, 16, 1), blk>>>(x, Wv, v, SEQ, 1024, HID,
                                             HID, HID, 1024, 0, 0, 0, 1, 0, 0);

    // RoPE
    {
        int tq = SEQ * NH * (HD / 2);
        rope_kernel<<<(tq + 255) / 256, blk>>>(q, cosT, sinT, NH);
        int tk = SEQ * NKV * (HD / 2);
        rope_kernel<<<(tk + 255) / 256, blk>>>(k, cosT, sinT, NKV);
    }

    // scores[h] = Q_h @ K_{h/2}^T  (NT, causal tile skip)
    gemm_tf32<true><<<dim3(16, 16, NH), blk>>>(q, k, sc, SEQ, SEQ, HD,
                                               NH * HD, NKV * HD, SEQ,
                                               HD, HD, (long long)SEQ * SEQ, 2, 1, 0);

    softmax_kernel<<<dim3(SEQ, NH), blk>>>(sc);

    // ctx[h] = P_h @ V_{h/2}  (NN, K clamped by causality)
    gemm_tf32<false><<<dim3(1, 16, NH), blk>>>(sc, v, ctx, SEQ, HD, SEQ,
                                               SEQ, NKV * HD, NH * HD,
                                               (long long)SEQ * SEQ, HD, HD, 2, 0, 1);

    // out = ctx @ Wo^T  (NT)
    gemm_tf32<true><<<dim3(16, 16, 1), blk>>>(ctx, Wo, out, SEQ, HID, NH * HD,
                                              NH * HD, NH * HD, HID, 0, 0, 0, 1, 0, 0);
}